// round 10
// baseline (speedup 1.0000x reference)
#include <cuda_runtime.h>
#include <cstdint>

// Problem shape (fixed by reference)
constexpr int EMBED = 256;
constexpr int BATCH = 64;
constexpr int BLOCK = 2048;
constexpr int NTOK  = BATCH * BLOCK;       // 131072 tokens

// Locked structure (measured best): 1 token/warp, logits stored immediately,
// .cs streaming stores, SHFL butterfly reduce. This round's variable:
// 256-bit loads AND stores (each lane owns one contiguous 32B chunk of the
// row) -> halves LDG+STG instruction count and store wavefronts. DRAM
// traffic unchanged (fully coalesced either way).

struct f8 { float v[8]; };

__device__ __forceinline__ f8 ldg_f8(const float* p) {
    f8 r;
    asm volatile("ld.global.nc.v8.f32 {%0,%1,%2,%3,%4,%5,%6,%7}, [%8];"
                 : "=f"(r.v[0]), "=f"(r.v[1]), "=f"(r.v[2]), "=f"(r.v[3]),
                   "=f"(r.v[4]), "=f"(r.v[5]), "=f"(r.v[6]), "=f"(r.v[7])
                 : "l"(p));
    return r;
}

__device__ __forceinline__ void stcs_f8(float* p, const f8& r) {
    asm volatile("st.global.cs.v8.f32 [%0], {%1,%2,%3,%4,%5,%6,%7,%8};"
                 :: "l"(p),
                    "f"(r.v[0]), "f"(r.v[1]), "f"(r.v[2]), "f"(r.v[3]),
                    "f"(r.v[4]), "f"(r.v[5]), "f"(r.v[6]), "f"(r.v[7])
                 : "memory");
}

__global__ __launch_bounds__(256)
void embed_softmax_kernel(const int* __restrict__ idx,
                          const float* __restrict__ emb,
                          float* __restrict__ out) {
    const int warp = (blockIdx.x * blockDim.x + threadIdx.x) >> 5;
    const int lane = threadIdx.x & 31;
    if (warp >= NTOK) return;

    const int row = __ldg(idx + warp);

    // one 256-bit load per lane covers the whole 1KB row across the warp
    f8 a = ldg_f8(emb + (size_t)row * EMBED + lane * 8);

    float* __restrict__ logit_dst = out + (size_t)warp * EMBED + lane * 8;
    float* __restrict__ prob_dst  = logit_dst + (size_t)NTOK * EMBED;

    // start the write stream immediately: logits are a straight copy
    stcs_f8(logit_dst, a);

    f8 e;
    #pragma unroll
    for (int i = 0; i < 8; i++) e.v[i] = __expf(a.v[i]);

    float s = ((e.v[0] + e.v[1]) + (e.v[2] + e.v[3]))
            + ((e.v[4] + e.v[5]) + (e.v[6] + e.v[7]));
    #pragma unroll
    for (int o = 16; o > 0; o >>= 1)
        s += __shfl_xor_sync(0xFFFFFFFFu, s, o);

    const float inv = __frcp_rn(s);
    #pragma unroll
    for (int i = 0; i < 8; i++) e.v[i] *= inv;

    stcs_f8(prob_dst, e);
}

extern "C" void kernel_launch(void* const* d_in, const int* in_sizes, int n_in,
                              void* d_out, int out_size) {
    const int* idx;
    const float* emb;
    if (in_sizes[0] == NTOK) {
        idx = (const int*)d_in[0];
        emb = (const float*)d_in[1];
    } else {
        idx = (const int*)d_in[1];
        emb = (const float*)d_in[0];
    }
    float* out = (float*)d_out;

    // one warp per token: 131072 warps -> 256-thread blocks, 8 warps each
    const int threads = 256;
    const int blocks = (NTOK * 32) / threads;  // 16384
    embed_softmax_kernel<<<blocks, threads>>>(idx, emb, out);
}

// round 11
// speedup vs baseline: 1.0430x; 1.0430x over previous
#include <cuda_runtime.h>
#include <cstdint>

// FINAL locked config — measured best across 9 benched variants (55.6us ncu
// kernel time). The problem is at the HBM mixed random-read/streaming-write
// floor: ~310MB DRAM traffic/launch (256MB compulsory writes + ~55MB gather
// misses against a 128MB table in 126MB L2) at ~5.5TB/s achieved. Every
// cache-policy, load/store-width, MLP and reduction variant measured
// neutral-to-worse with identical DRAM traffic.
constexpr int EMBED = 256;
constexpr int BATCH = 64;
constexpr int BLOCK = 2048;
constexpr int NTOK  = BATCH * BLOCK;       // 131072 tokens
constexpr int VEC_PER_ROW = EMBED / 4;     // 64 float4 per row

__device__ __forceinline__ void stcs_f4(float4* p, float4 v) {
    // streaming store: evict-first in L2 (best-measured store policy)
    asm volatile("st.global.cs.v4.f32 [%0], {%1,%2,%3,%4};"
                 :: "l"(p), "f"(v.x), "f"(v.y), "f"(v.z), "f"(v.w) : "memory");
}

__global__ __launch_bounds__(256)
void embed_softmax_kernel(const int* __restrict__ idx,
                          const float* __restrict__ emb,
                          float* __restrict__ out) {
    const int warp = (blockIdx.x * blockDim.x + threadIdx.x) >> 5;
    const int lane = threadIdx.x & 31;
    if (warp >= NTOK) return;

    const int row = __ldg(idx + warp);
    const float4* __restrict__ src =
        reinterpret_cast<const float4*>(emb + (size_t)row * EMBED);

    // 64 float4 per row, 32 lanes -> 2 vec loads per lane (fully coalesced 1KB)
    float4 a = __ldg(src + lane);
    float4 b = __ldg(src + 32 + lane);

    float e0 = __expf(a.x), e1 = __expf(a.y), e2 = __expf(a.z), e3 = __expf(a.w);
    float e4 = __expf(b.x), e5 = __expf(b.y), e6 = __expf(b.z), e7 = __expf(b.w);

    float s = ((e0 + e1) + (e2 + e3)) + ((e4 + e5) + (e6 + e7));
    #pragma unroll
    for (int o = 16; o > 0; o >>= 1)
        s += __shfl_xor_sync(0xFFFFFFFFu, s, o);

    const float inv = __frcp_rn(s);

    float4* __restrict__ logit_dst =
        reinterpret_cast<float4*>(out) + (size_t)warp * VEC_PER_ROW;
    float4* __restrict__ prob_dst =
        logit_dst + (size_t)NTOK * VEC_PER_ROW;

    // logits: straight copy of gathered row
    stcs_f4(logit_dst + lane, a);
    stcs_f4(logit_dst + 32 + lane, b);

    // probs: exp * inv_sum
    stcs_f4(prob_dst + lane,      make_float4(e0 * inv, e1 * inv, e2 * inv, e3 * inv));
    stcs_f4(prob_dst + 32 + lane, make_float4(e4 * inv, e5 * inv, e6 * inv, e7 * inv));
}

extern "C" void kernel_launch(void* const* d_in, const int* in_sizes, int n_in,
                              void* d_out, int out_size) {
    const int* idx;
    const float* emb;
    if (in_sizes[0] == NTOK) {
        idx = (const int*)d_in[0];
        emb = (const float*)d_in[1];
    } else {
        idx = (const int*)d_in[1];
        emb = (const float*)d_in[0];
    }
    float* out = (float*)d_out;

    // one warp per token: 131072 warps -> 256-thread blocks, 8 warps each
    const int threads = 256;
    const int blocks = (NTOK * 32) / threads;  // 16384
    embed_softmax_kernel<<<blocks, threads>>>(idx, emb, out);
}